// round 4
// baseline (speedup 1.0000x reference)
#include <cuda_runtime.h>
#include <cstdint>
#include <math.h>

#define LC   2048
#define CINV 0.35355339059327373f   // 1/(2*sqrt(2))

typedef unsigned long long u64;

// Scratch: transposed weights [which][k][i*64+o], corrections [k][which][b][o]
__device__ float g_wt[2][(size_t)LC * 4096];
__device__ float g_ad[(size_t)LC * 4096];

// packed f32x2 FMA: acc(2 lanes) += a(2 lanes) * b(2 lanes)
__device__ __forceinline__ void fma2(u64& acc, u64 a, u64 b) {
    asm("fma.rn.f32x2 %0, %1, %2, %0;" : "+l"(acc) : "l"(a), "l"(b));
}
__device__ __forceinline__ float lo32(u64 v) { return __uint_as_float((unsigned)v); }
__device__ __forceinline__ float hi32(u64 v) { return __uint_as_float((unsigned)(v >> 32)); }

__device__ __forceinline__ float gelu_tanh(float v) {
    float z = 0.7978845608028654f * (v + 0.044715f * v * v * v);
    float t;
    asm("tanh.approx.f32 %0, %1;" : "=f"(t) : "f"(z));
    return 0.5f * v * (1.0f + t);
}

// ---------------------------------------------------------------------------
// Kernel 1: transpose w_approx / w_detail from (i,o,l) -> (l, i*64+o)
// ---------------------------------------------------------------------------
__global__ void transpose_w_kernel(const float* __restrict__ wA,
                                   const float* __restrict__ wD) {
    __shared__ float tile[32][33];
    const float* src = (blockIdx.z == 0) ? wA : wD;
    float* dst = g_wt[blockIdx.z];
    int lbase  = blockIdx.x * 32;
    int iobase = blockIdx.y * 32;
    int tx = threadIdx.x, ty = threadIdx.y;   // block (32, 8)
#pragma unroll
    for (int r = 0; r < 32; r += 8)
        tile[ty + r][tx] = src[(size_t)(iobase + ty + r) * LC + (lbase + tx)];
    __syncthreads();
#pragma unroll
    for (int r = 0; r < 32; r += 8)
        dst[(size_t)(lbase + ty + r) * 4096 + (iobase + tx)] = tile[tx][ty + r];
}

// ---------------------------------------------------------------------------
// Kernel 2: fused u/v + corrections.  One block per k, 256 threads.
//   us[which][b][i] = c*(sum_{j<4} x +/- sum_{j>=4} x)
//   g_ad[k][which][b][o] = c*( sum_i us[b][i]*W[i][o]  -  us[b][o] )
// Weights K-paired: wp[which][i2*64+o] = {W[2*i2][o], W[2*i2+1][o]} (u64).
// ---------------------------------------------------------------------------
__global__ __launch_bounds__(256, 4) void stagea_kernel(const float* __restrict__ x) {
    __shared__ float wpf[8192];   // [2][32 i2][64 o][2]
    __shared__ float us[4096];    // [2][32 b][64 i]

    const int k = blockIdx.x, tid = threadIdx.x;

    for (int p = tid; p < 4096; p += 256) {
        int i = p >> 6, o = p & 63;
        int dst = (i >> 1) * 128 + o * 2 + (i & 1);
        wpf[dst]        = g_wt[0][(size_t)k * 4096 + p];
        wpf[4096 + dst] = g_wt[1][(size_t)k * 4096 + p];
    }
    for (int p = tid; p < 2048; p += 256) {
        int i = p & 63, b = p >> 6;
        const float* xp = x + ((size_t)b * 16384 + (size_t)k * 8) * 64 + i;
        float e = 0.f, d = 0.f;
#pragma unroll
        for (int j = 0; j < 4; j++) { e += xp[j * 64]; d += xp[(j + 4) * 64]; }
        us[b * 64 + i]        = CINV * (e + d);
        us[2048 + b * 64 + i] = CINV * (e - d);
    }
    __syncthreads();

    const int which = tid >> 7;
    const int r  = tid & 127;
    const int b0 = (r >> 4) * 4;
    const int og = r & 15;
    const u64*   WP = (const u64*)(wpf + which * 4096);
    const float* U  = us + which * 2048;

    u64 acc[4][4] = {};
#pragma unroll 4
    for (int i2 = 0; i2 < 32; i2++) {
        u64 w2[4], u2[4];
#pragma unroll
        for (int oo = 0; oo < 4; oo++) w2[oo] = WP[i2 * 64 + og + 16 * oo];
#pragma unroll
        for (int bb = 0; bb < 4; bb++)
            u2[bb] = *(const u64*)(U + (b0 + bb) * 64 + 2 * i2);
#pragma unroll
        for (int bb = 0; bb < 4; bb++)
#pragma unroll
            for (int oo = 0; oo < 4; oo++)
                fma2(acc[bb][oo], u2[bb], w2[oo]);
    }

    float* adg = g_ad + (size_t)k * 4096 + which * 2048;
#pragma unroll
    for (int bb = 0; bb < 4; bb++)
#pragma unroll
        for (int oo = 0; oo < 4; oo++) {
            int o = og + 16 * oo;
            float s = lo32(acc[bb][oo]) + hi32(acc[bb][oo]);
            adg[(b0 + bb) * 64 + o] = CINV * (s - U[(b0 + bb) * 64 + o]);
        }
}

// ---------------------------------------------------------------------------
// Kernel 3: main GEMM + epilogue via packed f32x2 FFMA.
// One block per k, 1024 threads. C[256 rows x 64] = X . (W_skip + I),
// out = gelu(C + A + sgn*D + bias). Thread tile: 8 rows x {cg, cg+32}.
// K paired into f32x2 lanes: both operands contiguous u64 loads, no packing.
// ---------------------------------------------------------------------------
__global__ __launch_bounds__(1024, 1) void main_kernel(
    const float* __restrict__ x, const float* __restrict__ Ws,
    const float* __restrict__ bsk, float* __restrict__ out)
{
    extern __shared__ float sm[];
    float* xs   = sm;            // 32 b * 520 (8 rows x 64 + pad 8)
    float* w2f  = sm + 16640;    // [32 kk2][64 c][2]
    float* ads  = sm + 20736;    // [2 which][32 b][64 o]
    float* bias = sm + 24832;    // 64

    const int k = blockIdx.x, tid = threadIdx.x;

    for (int i = tid; i < 4096; i += 1024) {
        int kk = i >> 6, c = i & 63;
        float v = Ws[i] + ((kk == c) ? 1.f : 0.f);
        w2f[(kk >> 1) * 128 + c * 2 + (kk & 1)] = v;
    }
    for (int i = tid; i < 4096; i += 1024)
        ads[i] = g_ad[(size_t)k * 4096 + i];
    if (tid < 64) bias[tid] = bsk[tid];

    const float4* x4  = (const float4*)x;
    float4*       xs4 = (float4*)xs;
#pragma unroll
    for (int it = 0; it < 4; it++) {
        int idx = tid + it * 1024;          // 0..4095 float4s
        int b = idx >> 7, r = idx & 127;
        xs4[b * 130 + r] = x4[(size_t)b * 262144 + (size_t)k * 128 + r];
    }
    __syncthreads();

    const int b  = tid >> 5;
    const int cg = tid & 31;
    const float* xb = xs + b * 520;
    const u64*   W2 = (const u64*)w2f;

    u64 acc[8][2] = {};
#pragma unroll 8
    for (int kk2 = 0; kk2 < 32; kk2++) {
        u64 wA = W2[kk2 * 64 + cg];
        u64 wB = W2[kk2 * 64 + cg + 32];
#pragma unroll
        for (int j = 0; j < 8; j++) {
            u64 xj = *(const u64*)(xb + j * 64 + kk2 * 2);
            fma2(acc[j][0], xj, wA);
            fma2(acc[j][1], xj, wB);
        }
    }

    const float A0 = ads[b * 64 + cg],        A1 = ads[b * 64 + cg + 32];
    const float D0 = ads[2048 + b * 64 + cg], D1 = ads[2048 + b * 64 + cg + 32];
    const float B0 = bias[cg],                B1 = bias[cg + 32];
    float* op = out + ((size_t)b * 16384 + (size_t)k * 8) * 64;
#pragma unroll
    for (int j = 0; j < 8; j++) {
        float sgn = (j < 4) ? 1.f : -1.f;
        float s0 = lo32(acc[j][0]) + hi32(acc[j][0]) + A0 + sgn * D0 + B0;
        float s1 = lo32(acc[j][1]) + hi32(acc[j][1]) + A1 + sgn * D1 + B1;
        op[j * 64 + cg]      = gelu_tanh(s0);
        op[j * 64 + cg + 32] = gelu_tanh(s1);
    }
}

extern "C" void kernel_launch(void* const* d_in, const int* in_sizes, int n_in,
                              void* d_out, int out_size) {
    const float* x  = (const float*)d_in[0];   // (32, 16384, 64)
    const float* wA = (const float*)d_in[1];   // (64, 64, 2048)
    const float* wD = (const float*)d_in[2];   // (64, 64, 2048)
    const float* Ws = (const float*)d_in[3];   // (64, 64)
    const float* bs = (const float*)d_in[4];   // (64,)
    float* out = (float*)d_out;

    cudaFuncSetAttribute(main_kernel,
        cudaFuncAttributeMaxDynamicSharedMemorySize, 99584);

    dim3 tb(32, 8), tg(LC / 32, 4096 / 32, 2);
    transpose_w_kernel<<<tg, tb>>>(wA, wD);

    stagea_kernel<<<LC, 256>>>(x);

    main_kernel<<<LC, 1024, 99584>>>(x, Ws, bs, out);
}

// round 5
// speedup vs baseline: 1.4163x; 1.4163x over previous
#include <cuda_runtime.h>
#include <cstdint>
#include <math.h>

#define LC   2048
#define CINV 0.35355339059327373f   // 1/(2*sqrt(2))

// Scratch: transposed weights [which][k][i*64+o], corrections [k][which][b][o]
__device__ float g_wt[2][(size_t)LC * 4096];
__device__ float g_ad[(size_t)LC * 4096];

__device__ __forceinline__ float gelu_tanh(float v) {
    float z = 0.7978845608028654f * (v + 0.044715f * v * v * v);
    float t;
    asm("tanh.approx.f32 %0, %1;" : "=f"(t) : "f"(z));
    return 0.5f * v * (1.0f + t);
}

// ---------------------------------------------------------------------------
// Kernel 1: transpose w_approx / w_detail from (i,o,l) -> (l, i*64+o)
// ---------------------------------------------------------------------------
__global__ void transpose_w_kernel(const float* __restrict__ wA,
                                   const float* __restrict__ wD) {
    __shared__ float tile[32][33];
    const float* src = (blockIdx.z == 0) ? wA : wD;
    float* dst = g_wt[blockIdx.z];
    int lbase  = blockIdx.x * 32;
    int iobase = blockIdx.y * 32;
    int tx = threadIdx.x, ty = threadIdx.y;   // block (32, 8)
#pragma unroll
    for (int r = 0; r < 32; r += 8)
        tile[ty + r][tx] = src[(size_t)(iobase + ty + r) * LC + (lbase + tx)];
    __syncthreads();
#pragma unroll
    for (int r = 0; r < 32; r += 8)
        dst[(size_t)(lbase + ty + r) * 4096 + (iobase + tx)] = tile[tx][ty + r];
}

// ---------------------------------------------------------------------------
// Kernel 2: fused u/v + corrections.  One block per k, 256 threads.
//   us[which][i*33+b] = c*(sum_{j<4} x[8k+j] +/- sum_{j>=4} x[8k+j])  (i-major, pad 33)
//   g_ad[k][which][b][o] = c*( sum_i us[b][i]*W_t[k][i][o]  -  us[b][o] )
// Inner loop: proven R2 scalar 4x4 register tile (4 batches x 4 outputs).
// ---------------------------------------------------------------------------
__global__ __launch_bounds__(256, 4) void stagea_kernel(const float* __restrict__ x) {
    extern __shared__ float sm[];
    float* wsm = sm;           // [2][4096]   32 KB
    float* us  = sm + 8192;    // [2][i*33+b] 16.9 KB

    const int k = blockIdx.x, tid = threadIdx.x;

    for (int i = tid; i < 4096; i += 256) {
        wsm[i]        = g_wt[0][(size_t)k * 4096 + i];
        wsm[4096 + i] = g_wt[1][(size_t)k * 4096 + i];
    }
    // u/v directly from x (fused; saves the separate uv kernel + scratch)
    for (int p = tid; p < 2048; p += 256) {
        int i = p & 63, b = p >> 6;
        const float* xp = x + ((size_t)b * 16384 + (size_t)k * 8) * 64 + i;
        float e = 0.f, d = 0.f;
#pragma unroll
        for (int j = 0; j < 4; j++) { e += xp[j * 64]; d += xp[(j + 4) * 64]; }
        us[i * 33 + b]        = CINV * (e + d);
        us[2112 + i * 33 + b] = CINV * (e - d);
    }
    __syncthreads();

    const int which = tid >> 7;
    const int r  = tid & 127;
    const int b0 = (r >> 4) * 4;
    const int og = (r & 15) * 4;
    const float* W = wsm + which * 4096;
    const float* U = us + which * 2112;

    float acc[4][4] = {};
#pragma unroll 8
    for (int i = 0; i < 64; i++) {
        float4 w4 = *(const float4*)(W + i * 64 + og);
#pragma unroll
        for (int bb = 0; bb < 4; bb++) {
            float uu = U[i * 33 + b0 + bb];
            acc[bb][0] = fmaf(uu, w4.x, acc[bb][0]);
            acc[bb][1] = fmaf(uu, w4.y, acc[bb][1]);
            acc[bb][2] = fmaf(uu, w4.z, acc[bb][2]);
            acc[bb][3] = fmaf(uu, w4.w, acc[bb][3]);
        }
    }
    float* adg = g_ad + (size_t)k * 4096 + which * 2048;
#pragma unroll
    for (int bb = 0; bb < 4; bb++)
#pragma unroll
        for (int c = 0; c < 4; c++)
            adg[(b0 + bb) * 64 + og + c] =
                CINV * (acc[bb][c] - U[(og + c) * 33 + b0 + bb]);
}

// ---------------------------------------------------------------------------
// Kernel 3: main GEMM + epilogue (scalar FFMA, proven R2 inner loop).
// Grid 4096: block = (k, half). 128 rows (16 batches x 8) x 64 cols per block.
// 256 threads, 8x4 register tile, 3 CTAs/SM -> 24 warps.
// ---------------------------------------------------------------------------
__global__ __launch_bounds__(256, 3) void main_kernel(
    const float* __restrict__ x, const float* __restrict__ Ws,
    const float* __restrict__ bsk, float* __restrict__ out)
{
    extern __shared__ float sm[];
    float* xs   = sm;            // 16 b * 520 = 8320
    float* wsk  = sm + 8320;     // 4096  (W_skip + I)
    float* ads  = sm + 12416;    // 2048  [which][16 b][64 o]
    float* bias = sm + 14464;    // 64    (total 14528 floats = 58112 B)

    const int k    = blockIdx.x >> 1;
    const int half = blockIdx.x & 1;
    const int tid  = threadIdx.x;

    for (int i = tid; i < 4096; i += 256) {
        float v = Ws[i];
        if ((i >> 6) == (i & 63)) v += 1.0f;
        wsk[i] = v;
    }
    for (int i = tid; i < 2048; i += 256) {
        int which = i >> 10, bl = (i >> 6) & 15, o = i & 63;
        ads[i] = g_ad[(size_t)k * 4096 + which * 2048 + (half * 16 + bl) * 64 + o];
    }
    if (tid < 64) bias[tid] = bsk[tid];

    const float4* x4  = (const float4*)x;
    float4*       xs4 = (float4*)xs;
#pragma unroll
    for (int it = 0; it < 8; it++) {
        int idx = tid + it * 256;           // 0..2047 float4s
        int bl = idx >> 7, r = idx & 127;
        int b  = half * 16 + bl;
        xs4[bl * 130 + r] = x4[(size_t)b * 262144 + (size_t)k * 128 + r];
    }
    __syncthreads();

    const int bl = tid >> 4;
    const int cg = (tid & 15) << 2;
    const float* xb = xs + bl * 520;

    float acc[8][4] = {};
#pragma unroll 8
    for (int kk = 0; kk < 64; kk += 2) {
        float4 w0 = *(const float4*)(wsk + kk * 64 + cg);
        float4 w1 = *(const float4*)(wsk + (kk + 1) * 64 + cg);
        float2 xv[8];
#pragma unroll
        for (int j = 0; j < 8; j++)
            xv[j] = *(const float2*)(xb + j * 64 + kk);
#pragma unroll
        for (int j = 0; j < 8; j++) {
            acc[j][0] = fmaf(xv[j].x, w0.x, acc[j][0]);
            acc[j][0] = fmaf(xv[j].y, w1.x, acc[j][0]);
            acc[j][1] = fmaf(xv[j].x, w0.y, acc[j][1]);
            acc[j][1] = fmaf(xv[j].y, w1.y, acc[j][1]);
            acc[j][2] = fmaf(xv[j].x, w0.z, acc[j][2]);
            acc[j][2] = fmaf(xv[j].y, w1.z, acc[j][2]);
            acc[j][3] = fmaf(xv[j].x, w0.w, acc[j][3]);
            acc[j][3] = fmaf(xv[j].y, w1.w, acc[j][3]);
        }
    }

    float4 A  = *(const float4*)(ads + bl * 64 + cg);
    float4 Dv = *(const float4*)(ads + 1024 + bl * 64 + cg);
    float4 Bb = *(const float4*)(bias + cg);
    const int b = half * 16 + bl;
    float* op = out + ((size_t)b * 16384 + (size_t)k * 8) * 64 + cg;
#pragma unroll
    for (int j = 0; j < 8; j++) {
        float sgn = (j < 4) ? 1.f : -1.f;
        float4 rv;
        rv.x = gelu_tanh(acc[j][0] + A.x + sgn * Dv.x + Bb.x);
        rv.y = gelu_tanh(acc[j][1] + A.y + sgn * Dv.y + Bb.y);
        rv.z = gelu_tanh(acc[j][2] + A.z + sgn * Dv.z + Bb.z);
        rv.w = gelu_tanh(acc[j][3] + A.w + sgn * Dv.w + Bb.w);
        *(float4*)(op + j * 64) = rv;
    }
}

extern "C" void kernel_launch(void* const* d_in, const int* in_sizes, int n_in,
                              void* d_out, int out_size) {
    const float* x  = (const float*)d_in[0];   // (32, 16384, 64)
    const float* wA = (const float*)d_in[1];   // (64, 64, 2048)
    const float* wD = (const float*)d_in[2];   // (64, 64, 2048)
    const float* Ws = (const float*)d_in[3];   // (64, 64)
    const float* bs = (const float*)d_in[4];   // (64,)
    float* out = (float*)d_out;

    cudaFuncSetAttribute(stagea_kernel,
        cudaFuncAttributeMaxDynamicSharedMemorySize, 49664);
    cudaFuncSetAttribute(main_kernel,
        cudaFuncAttributeMaxDynamicSharedMemorySize, 58112);

    dim3 tb(32, 8), tg(LC / 32, 4096 / 32, 2);
    transpose_w_kernel<<<tg, tb>>>(wA, wD);

    stagea_kernel<<<LC, 256, 49664>>>(x);

    main_kernel<<<2 * LC, 256, 58112>>>(x, Ws, bs, out);
}